// round 5
// baseline (speedup 1.0000x reference)
#include <cuda_runtime.h>
#include <cuda_fp16.h>
#include <cstdint>

#define NN 50000
#define NE 800000
#define NT (NE / 128)

// ---------------- device scratch ----------------
__device__ __align__(16) __half g_WPQh[128 * 256];   // fused node weights, fp16 [k][col]
__device__ __align__(16) __half g_W3h[128 * 128];    // W3 fp16 [k][n]
__device__ __align__(16) float  g_BPQ[256];
__device__ __align__(16) float  g_PQ[(size_t)NN * 256];
__device__ int g_cnt[NN];
__device__ int g_cur[NN];
__device__ int g_esrc[NE];
__device__ int g_edst[NE];

// ---------------- helpers ----------------
__device__ __forceinline__ uint32_t smem_u32(const void* p) {
    uint32_t a;
    asm("{ .reg .u64 t; cvta.to.shared.u64 t, %1; cvt.u32.u64 %0, t; }" : "=r"(a) : "l"(p));
    return a;
}
__device__ __forceinline__ void ldsm_x4(uint32_t* r, uint32_t addr) {
    asm volatile("ldmatrix.sync.aligned.m8n8.x4.shared.b16 {%0,%1,%2,%3}, [%4];"
                 : "=r"(r[0]), "=r"(r[1]), "=r"(r[2]), "=r"(r[3]) : "r"(addr));
}
__device__ __forceinline__ void ldsm_x2t(uint32_t* r, uint32_t addr) {
    asm volatile("ldmatrix.sync.aligned.m8n8.x2.trans.shared.b16 {%0,%1}, [%2];"
                 : "=r"(r[0]), "=r"(r[1]) : "r"(addr));
}
__device__ __forceinline__ void mma16816(float* d, const uint32_t* a, const uint32_t* b) {
    asm volatile(
        "mma.sync.aligned.m16n8k16.row.col.f32.f16.f16.f32 "
        "{%0,%1,%2,%3}, {%4,%5,%6,%7}, {%8,%9}, {%0,%1,%2,%3};"
        : "+f"(d[0]), "+f"(d[1]), "+f"(d[2]), "+f"(d[3])
        : "r"(a[0]), "r"(a[1]), "r"(a[2]), "r"(a[3]), "r"(b[0]), "r"(b[1]));
}

// ---------------- trivial init kernels ----------------
__global__ void k_zero_out(float4* out, int n4) {
    int i = blockIdx.x * blockDim.x + threadIdx.x;
    if (i < n4) out[i] = make_float4(0.f, 0.f, 0.f, 0.f);
}
__global__ void k_zero_cnt() {
    int i = blockIdx.x * blockDim.x + threadIdx.x;
    if (i < NN) g_cnt[i] = 0;
}

// ---------------- weight prep ----------------
__global__ void k_prep_w(const float* __restrict__ W1, const float* __restrict__ b1,
                         const float* __restrict__ W2, const float* __restrict__ b2) {
    __shared__ float w1row[128];
    int i = blockIdx.x;
    if (threadIdx.x < 128) w1row[threadIdx.x] = W1[i * 128 + threadIdx.x];
    __syncthreads();
    int j = threadIdx.x;
    float acc = 0.f;
    if (j < 128) {
        for (int k = 0; k < 128; k++)
            acc += w1row[k] * (W2[k * 128 + j] - W2[(k + 128) * 128 + j]);
    } else {
        int jj = j - 128;
        for (int k = 0; k < 128; k++)
            acc += w1row[k] * W2[(k + 128) * 128 + jj];
    }
    g_WPQh[i * 256 + j] = __float2half_rn(acc);
    if (i == 0) {
        float b = 0.f;
        if (j < 128) {
            for (int k = 0; k < 128; k++)
                b += b1[k] * (W2[k * 128 + j] - W2[(k + 128) * 128 + j]);
            b += b2[j];
        } else {
            int jj = j - 128;
            for (int k = 0; k < 128; k++)
                b += b1[k] * W2[(k + 128) * 128 + jj];
        }
        g_BPQ[j] = b;
    }
}
__global__ void k_prep_w3(const float* __restrict__ W3) {
    int i = blockIdx.x * blockDim.x + threadIdx.x;
    if (i < 16384) g_W3h[i] = __float2half_rn(W3[i]);
}

// ---------------- node GEMM (HMMA, A=x split hi/lo exact, B=WPQ fp16) ----------------
// tile 64 rows x 256 cols, K=128. 8 warps: warp grid 2(M) x 4(N), warp tile 32x64.
// smem: Ah [64][128]f16 @0 (16KB), Al @16384, B [128][256]f16 @32768 (64KB)
#define nAh 0u
#define nAl 16384u
#define nB  32768u
#define NODE_SMEM 98304

__global__ void __launch_bounds__(256, 2) k_node_hmma(const float* __restrict__ x) {
    extern __shared__ char smb[];
    uint32_t sb = smem_u32(smb);
    int tid = threadIdx.x, lane = tid & 31, wid = tid >> 5;
    int row0 = blockIdx.x * 64;

    // stage B: WPQh [k][256], rows 512B, chunk swizzle cj^(k&7), cj in 0..31
#pragma unroll
    for (int q = tid; q < 4096; q += 256) {
        int k = q >> 5, cj = q & 31;
        uint4 pk = ((const uint4*)g_WPQh)[q];
        *(uint4*)(smb + nB + (uint32_t)(k * 512) + (uint32_t)((cj ^ (k & 7)) << 4)) = pk;
    }
    // stage A: x rows, split hi/lo
    {
        int r = tid & 63, hh = tid >> 6;          // hh 0..3: 32 k's each
        int row = row0 + r;
        const float4* xp = (const float4*)(x + (size_t)row * 128 + hh * 32);
        uint32_t rowbase = (uint32_t)(r * 256);
#pragma unroll
        for (int c = 0; c < 4; c++) {
            float4 f0, f1;
            if (row < NN) { f0 = xp[c * 2]; f1 = xp[c * 2 + 1]; }
            else { f0 = make_float4(0,0,0,0); f1 = f0; }
            float v[8] = {f0.x, f0.y, f0.z, f0.w, f1.x, f1.y, f1.z, f1.w};
            uint32_t hi[4], lo[4];
#pragma unroll
            for (int p = 0; p < 4; p++) {
                __half hx = __float2half_rn(v[p * 2]);
                __half hy = __float2half_rn(v[p * 2 + 1]);
                __half lx = __float2half_rn(v[p * 2] - __half2float(hx));
                __half ly = __float2half_rn(v[p * 2 + 1] - __half2float(hy));
                __half2 h2 = __halves2half2(hx, hy), l2 = __halves2half2(lx, ly);
                hi[p] = *(uint32_t*)&h2;
                lo[p] = *(uint32_t*)&l2;
            }
            int cj = hh * 4 + c;
            uint32_t off = rowbase + (uint32_t)((cj ^ (r & 7)) << 4);
            *(uint4*)(smb + nAh + off) = make_uint4(hi[0], hi[1], hi[2], hi[3]);
            *(uint4*)(smb + nAl + off) = make_uint4(lo[0], lo[1], lo[2], lo[3]);
        }
    }
    __syncthreads();

    int m0 = (wid & 1) * 32;
    int n0 = (wid >> 1) * 64;
    float acc[2][8][4];
#pragma unroll
    for (int a = 0; a < 2; a++)
#pragma unroll
        for (int b = 0; b < 8; b++)
#pragma unroll
            for (int c = 0; c < 4; c++) acc[a][b][c] = 0.f;

    int arow0 = m0 + (lane & 15), arow1 = arow0 + 16;
    int bk_lane = lane & 15;
#pragma unroll
    for (int ks = 0; ks < 8; ks++) {
        int chunk = ks * 2 + (lane >> 4);
        uint32_t a0a = sb + nAh + (uint32_t)(arow0 * 256) + (uint32_t)((chunk ^ (arow0 & 7)) << 4);
        uint32_t a1a = sb + nAh + (uint32_t)(arow1 * 256) + (uint32_t)((chunk ^ (arow1 & 7)) << 4);
        uint32_t ah0[4], ah1[4], al0[4], al1[4];
        ldsm_x4(ah0, a0a);
        ldsm_x4(ah1, a1a);
        ldsm_x4(al0, a0a + 16384u);
        ldsm_x4(al1, a1a + 16384u);
        int bk = ks * 16 + bk_lane;
        uint32_t brow = sb + nB + (uint32_t)(bk * 512);
        int bsw = bk & 7;
#pragma unroll
        for (int nt = 0; nt < 8; nt++) {
            uint32_t bfr[2];
            ldsm_x2t(bfr, brow + (uint32_t)((((n0 >> 3) + nt) ^ bsw) << 4));
            mma16816(acc[0][nt], ah0, bfr);
            mma16816(acc[1][nt], ah1, bfr);
            mma16816(acc[0][nt], al0, bfr);
            mma16816(acc[1][nt], al1, bfr);
        }
    }

    // epilogue: + bias, direct STG.64 to g_PQ
    {
        int cc = 2 * (lane & 3), rr = lane >> 2;
#pragma unroll
        for (int nt = 0; nt < 8; nt++) {
            int c_ = n0 + nt * 8 + cc;
            float2 bb = *(const float2*)&g_BPQ[c_];
#pragma unroll
            for (int mt = 0; mt < 2; mt++) {
                int r_ = row0 + m0 + mt * 16 + rr;
                if (r_ < NN)
                    *(float2*)&g_PQ[(size_t)r_ * 256 + c_] =
                        make_float2(acc[mt][nt][0] + bb.x, acc[mt][nt][1] + bb.y);
                if (r_ + 8 < NN)
                    *(float2*)&g_PQ[(size_t)(r_ + 8) * 256 + c_] =
                        make_float2(acc[mt][nt][2] + bb.x, acc[mt][nt][3] + bb.y);
            }
        }
    }
}

// ---------------- CSR build ----------------
__global__ void k_hist(const int* __restrict__ ei) {
    int e = blockIdx.x * blockDim.x + threadIdx.x;
    if (e < NE) atomicAdd(&g_cnt[ei[NE + e]], 1);
}
__global__ void k_scan() {
    __shared__ int s[1024];
    const int CH = 49;
    int t = threadIdx.x;
    int start = t * CH;
    int sum = 0;
    for (int i = 0; i < CH; i++) {
        int idx = start + i;
        if (idx < NN) sum += g_cnt[idx];
    }
    s[t] = sum;
    __syncthreads();
    for (int d = 1; d < 1024; d <<= 1) {
        int v = (t >= d) ? s[t - d] : 0;
        __syncthreads();
        s[t] += v;
        __syncthreads();
    }
    int run = s[t] - sum;
    for (int i = 0; i < CH; i++) {
        int idx = start + i;
        if (idx < NN) {
            g_cur[idx] = run;
            run += g_cnt[idx];
        }
    }
}
__global__ void k_scatter(const int* __restrict__ ei) {
    int e = blockIdx.x * blockDim.x + threadIdx.x;
    if (e < NE) {
        int d = ei[NE + e];
        int sr = ei[e];
        int pos = atomicAdd(&g_cur[d], 1);
        g_esrc[pos] = sr;
        g_edst[pos] = d;
    }
}

// ---------------- HMMA edge kernel (single-pass fp16) ----------------
// smem: A fp16 [128r][128k] @0 (32KB), B fp16 [128k][128n] @32768 (32KB),
//       accf overlay f32 [128][132] @0 (67584, A+B dead after MMA),
//       b3s @67584, sdst @68096
#define oA  0u
#define oB  32768u
#define oB3 67584u
#define oSD 68096u
#define EDGE_SMEM 68608

__global__ void __launch_bounds__(256, 3) k_edge_mma(const float* __restrict__ b3,
                                                     float* __restrict__ out) {
    extern __shared__ char smb[];
    uint32_t sb = smem_u32(smb);
    int tid = threadIdx.x, lane = tid & 31, wid = tid >> 5;

    if (tid < 128) ((float*)(smb + oB3))[tid] = b3[tid];

    // stage B from pre-converted g_W3h: rows 256B, chunk swizzle cj^(k&7)
#pragma unroll
    for (int q = tid; q < 2048; q += 256) {
        int k = q >> 4, cj = q & 15;
        uint4 pk = ((const uint4*)g_W3h)[q];
        *(uint4*)(smb + oB + (uint32_t)(k * 256) + (uint32_t)((cj ^ (k & 7)) << 4)) = pk;
    }

    // build A = m1 = relu(P[dst] + Q[src]) fp16 (single precision pass)
    {
        int r = tid & 127, hh = tid >> 7;
        int e = blockIdx.x * 128 + r;
        int dst = g_edst[e];
        int src = g_esrc[e];
        if (hh == 0) ((int*)(smb + oSD))[r] = dst;
        const float4* pv = (const float4*)(g_PQ + (size_t)dst * 256) + hh * 16;
        const float4* qv = (const float4*)(g_PQ + (size_t)src * 256 + 128) + hh * 16;
        uint32_t rowbase = (uint32_t)(r * 256);
#pragma unroll
        for (int c = 0; c < 8; c++) {
            float4 a0 = pv[c * 2], b0 = qv[c * 2];
            float4 a1 = pv[c * 2 + 1], b1 = qv[c * 2 + 1];
            __half2 h0 = __floats2half2_rn(fmaxf(a0.x + b0.x, 0.f), fmaxf(a0.y + b0.y, 0.f));
            __half2 h1 = __floats2half2_rn(fmaxf(a0.z + b0.z, 0.f), fmaxf(a0.w + b0.w, 0.f));
            __half2 h2 = __floats2half2_rn(fmaxf(a1.x + b1.x, 0.f), fmaxf(a1.y + b1.y, 0.f));
            __half2 h3 = __floats2half2_rn(fmaxf(a1.z + b1.z, 0.f), fmaxf(a1.w + b1.w, 0.f));
            int cj = hh * 8 + c;
            uint32_t off = rowbase + (uint32_t)((cj ^ (r & 7)) << 4);
            *(uint4*)(smb + oA + off) =
                make_uint4(*(uint32_t*)&h0, *(uint32_t*)&h1, *(uint32_t*)&h2, *(uint32_t*)&h3);
        }
    }
    __syncthreads();

    // MMA: warp grid 4(M) x 2(N); warp tile 32x64; single pass
    int m0 = (wid & 3) * 32;
    int n0 = (wid >> 2) * 64;
    float acc[2][8][4];
#pragma unroll
    for (int a = 0; a < 2; a++)
#pragma unroll
        for (int b = 0; b < 8; b++)
#pragma unroll
            for (int c = 0; c < 4; c++) acc[a][b][c] = 0.f;

    int arow0 = m0 + (lane & 15), arow1 = arow0 + 16;
    int bk_lane = lane & 15;
#pragma unroll
    for (int ks = 0; ks < 8; ks++) {
        int chunk = ks * 2 + (lane >> 4);
        uint32_t ah0[4], ah1[4];
        ldsm_x4(ah0, sb + oA + (uint32_t)(arow0 * 256) + (uint32_t)((chunk ^ (arow0 & 7)) << 4));
        ldsm_x4(ah1, sb + oA + (uint32_t)(arow1 * 256) + (uint32_t)((chunk ^ (arow1 & 7)) << 4));
        int bk = ks * 16 + bk_lane;
        uint32_t brow = sb + oB + (uint32_t)(bk * 256);
        int bsw = bk & 7;
#pragma unroll
        for (int nt = 0; nt < 8; nt++) {
            uint32_t bfr[2];
            ldsm_x2t(bfr, brow + (uint32_t)((((n0 >> 3) + nt) ^ bsw) << 4));
            mma16816(acc[0][nt], ah0, bfr);
            mma16816(acc[1][nt], ah1, bfr);
        }
    }
    __syncthreads();

    // dump acc to accf [128][132] f32 (overlays A+B)
    float* accf = (float*)smb;
    {
        int rr = lane >> 2, cc = 2 * (lane & 3);
#pragma unroll
        for (int mt = 0; mt < 2; mt++)
#pragma unroll
            for (int nt = 0; nt < 8; nt++) {
                int r_ = m0 + mt * 16 + rr;
                int c_ = n0 + nt * 8 + cc;
                *(float2*)&accf[r_ * 132 + c_] = make_float2(acc[mt][nt][0], acc[mt][nt][1]);
                *(float2*)&accf[(r_ + 8) * 132 + c_] = make_float2(acc[mt][nt][2], acc[mt][nt][3]);
            }
    }
    __syncthreads();

    // epilogue: bias + relu + run-merged segmented max + atomicMax
    {
        int cg = tid & 31;
        int rg = tid >> 5;
        const float* b3s = (const float*)(smb + oB3);
        const int* sd = (const int*)(smb + oSD);
        float4 bias = *(const float4*)&b3s[cg * 4];
        int rbase = rg * 16;
        int curd = sd[rbase];
        float4 v = *(float4*)&accf[rbase * 132 + cg * 4];
        float4 mx = make_float4(fmaxf(v.x + bias.x, 0.f), fmaxf(v.y + bias.y, 0.f),
                                fmaxf(v.z + bias.z, 0.f), fmaxf(v.w + bias.w, 0.f));
#pragma unroll
        for (int i = 1; i < 16; i++) {
            int d = sd[rbase + i];
            float4 u = *(float4*)&accf[(rbase + i) * 132 + cg * 4];
            float4 w = make_float4(fmaxf(u.x + bias.x, 0.f), fmaxf(u.y + bias.y, 0.f),
                                   fmaxf(u.z + bias.z, 0.f), fmaxf(u.w + bias.w, 0.f));
            if (d != curd) {
                int* op = (int*)out + (size_t)curd * 128 + cg * 4;
                if (mx.x > 0.f) atomicMax(op + 0, __float_as_int(mx.x));
                if (mx.y > 0.f) atomicMax(op + 1, __float_as_int(mx.y));
                if (mx.z > 0.f) atomicMax(op + 2, __float_as_int(mx.z));
                if (mx.w > 0.f) atomicMax(op + 3, __float_as_int(mx.w));
                curd = d;
                mx = w;
            } else {
                mx.x = fmaxf(mx.x, w.x);
                mx.y = fmaxf(mx.y, w.y);
                mx.z = fmaxf(mx.z, w.z);
                mx.w = fmaxf(mx.w, w.w);
            }
        }
        int* op = (int*)out + (size_t)curd * 128 + cg * 4;
        if (mx.x > 0.f) atomicMax(op + 0, __float_as_int(mx.x));
        if (mx.y > 0.f) atomicMax(op + 1, __float_as_int(mx.y));
        if (mx.z > 0.f) atomicMax(op + 2, __float_as_int(mx.z));
        if (mx.w > 0.f) atomicMax(op + 3, __float_as_int(mx.w));
    }
}

// ---------------- launch ----------------
extern "C" void kernel_launch(void* const* d_in, const int* in_sizes, int n_in,
                              void* d_out, int out_size) {
    const float* x  = (const float*)d_in[0];
    const int*   ei = (const int*)d_in[1];
    const float* W1 = (const float*)d_in[2];
    const float* b1 = (const float*)d_in[3];
    const float* W2 = (const float*)d_in[4];
    const float* b2 = (const float*)d_in[5];
    const float* W3 = (const float*)d_in[6];
    const float* b3 = (const float*)d_in[7];
    float* out = (float*)d_out;

    cudaFuncSetAttribute(k_edge_mma, cudaFuncAttributeMaxDynamicSharedMemorySize, EDGE_SMEM);
    cudaFuncSetAttribute(k_node_hmma, cudaFuncAttributeMaxDynamicSharedMemorySize, NODE_SMEM);

    k_zero_out<<<(NN * 128 / 4 + 255) / 256, 256>>>((float4*)out, NN * 128 / 4);
    k_zero_cnt<<<(NN + 255) / 256, 256>>>();
    k_prep_w<<<128, 256>>>(W1, b1, W2, b2);
    k_prep_w3<<<64, 256>>>(W3);
    k_node_hmma<<<(NN + 63) / 64, 256, NODE_SMEM>>>(x);
    k_hist<<<NE / 256, 256>>>(ei);
    k_scan<<<1, 1024>>>();
    k_scatter<<<NE / 256, 256>>>(ei);
    k_edge_mma<<<NT, 256, EDGE_SMEM>>>(b3, out);
}

// round 6
// speedup vs baseline: 1.3150x; 1.3150x over previous
#include <cuda_runtime.h>
#include <cuda_fp16.h>
#include <cstdint>

#define NN 50000
#define NE 800000
#define NT (NE / 128)

// ---------------- device scratch ----------------
__device__ __align__(16) __half g_WPQh[128 * 256];   // fused node weights, fp16 [k][col]
__device__ __align__(16) __half g_W3h[128 * 128];    // W3 fp16 [k][n]
__device__ __align__(16) float  g_BPQ[256];
__device__ __align__(16) float  g_PQ[(size_t)NN * 256];
__device__ int g_cnt[NN];
__device__ int g_cur[NN];
__device__ int g_esrc[NE];
__device__ int g_edst[NE];

// ---------------- helpers ----------------
__device__ __forceinline__ uint32_t smem_u32(const void* p) {
    uint32_t a;
    asm("{ .reg .u64 t; cvta.to.shared.u64 t, %1; cvt.u32.u64 %0, t; }" : "=r"(a) : "l"(p));
    return a;
}
__device__ __forceinline__ void ldsm_x4(uint32_t* r, uint32_t addr) {
    asm volatile("ldmatrix.sync.aligned.m8n8.x4.shared.b16 {%0,%1,%2,%3}, [%4];"
                 : "=r"(r[0]), "=r"(r[1]), "=r"(r[2]), "=r"(r[3]) : "r"(addr));
}
__device__ __forceinline__ void ldsm_x2t(uint32_t* r, uint32_t addr) {
    asm volatile("ldmatrix.sync.aligned.m8n8.x2.trans.shared.b16 {%0,%1}, [%2];"
                 : "=r"(r[0]), "=r"(r[1]) : "r"(addr));
}
__device__ __forceinline__ void mma16816(float* d, const uint32_t* a, const uint32_t* b) {
    asm volatile(
        "mma.sync.aligned.m16n8k16.row.col.f32.f16.f16.f32 "
        "{%0,%1,%2,%3}, {%4,%5,%6,%7}, {%8,%9}, {%0,%1,%2,%3};"
        : "+f"(d[0]), "+f"(d[1]), "+f"(d[2]), "+f"(d[3])
        : "r"(a[0]), "r"(a[1]), "r"(a[2]), "r"(a[3]), "r"(b[0]), "r"(b[1]));
}

// ---------------- trivial init kernels ----------------
__global__ void k_zero_out(float4* out, int n4) {
    int i = blockIdx.x * blockDim.x + threadIdx.x;
    if (i < n4) out[i] = make_float4(0.f, 0.f, 0.f, 0.f);
}
__global__ void k_zero_cnt() {
    int i = blockIdx.x * blockDim.x + threadIdx.x;
    if (i < NN) g_cnt[i] = 0;
}

// ---------------- weight prep ----------------
__global__ void k_prep_w(const float* __restrict__ W1, const float* __restrict__ b1,
                         const float* __restrict__ W2, const float* __restrict__ b2) {
    __shared__ float w1row[128];
    int i = blockIdx.x;
    if (threadIdx.x < 128) w1row[threadIdx.x] = W1[i * 128 + threadIdx.x];
    __syncthreads();
    int j = threadIdx.x;
    float acc = 0.f;
    if (j < 128) {
        for (int k = 0; k < 128; k++)
            acc += w1row[k] * (W2[k * 128 + j] - W2[(k + 128) * 128 + j]);
    } else {
        int jj = j - 128;
        for (int k = 0; k < 128; k++)
            acc += w1row[k] * W2[(k + 128) * 128 + jj];
    }
    g_WPQh[i * 256 + j] = __float2half_rn(acc);
    if (i == 0) {
        float b = 0.f;
        if (j < 128) {
            for (int k = 0; k < 128; k++)
                b += b1[k] * (W2[k * 128 + j] - W2[(k + 128) * 128 + j]);
            b += b2[j];
        } else {
            int jj = j - 128;
            for (int k = 0; k < 128; k++)
                b += b1[k] * W2[(k + 128) * 128 + jj];
        }
        g_BPQ[j] = b;
    }
}
__global__ void k_prep_w3(const float* __restrict__ W3) {
    int i = blockIdx.x * blockDim.x + threadIdx.x;
    if (i < 16384) g_W3h[i] = __float2half_rn(W3[i]);
}

// ---------------- node GEMM (HMMA, A=x split hi/lo exact, B=WPQ fp16) ----------------
#define nAh 0u
#define nAl 16384u
#define nB  32768u
#define NODE_SMEM 98304

__global__ void __launch_bounds__(256, 2) k_node_hmma(const float* __restrict__ x) {
    extern __shared__ char smb[];
    uint32_t sb = smem_u32(smb);
    int tid = threadIdx.x, lane = tid & 31, wid = tid >> 5;
    int row0 = blockIdx.x * 64;

#pragma unroll
    for (int q = tid; q < 4096; q += 256) {
        int k = q >> 5, cj = q & 31;
        uint4 pk = ((const uint4*)g_WPQh)[q];
        *(uint4*)(smb + nB + (uint32_t)(k * 512) + (uint32_t)((cj ^ (k & 7)) << 4)) = pk;
    }
    {
        int r = tid & 63, hh = tid >> 6;
        int row = row0 + r;
        const float4* xp = (const float4*)(x + (size_t)row * 128 + hh * 32);
        uint32_t rowbase = (uint32_t)(r * 256);
#pragma unroll
        for (int c = 0; c < 4; c++) {
            float4 f0, f1;
            if (row < NN) { f0 = xp[c * 2]; f1 = xp[c * 2 + 1]; }
            else { f0 = make_float4(0,0,0,0); f1 = f0; }
            float v[8] = {f0.x, f0.y, f0.z, f0.w, f1.x, f1.y, f1.z, f1.w};
            uint32_t hi[4], lo[4];
#pragma unroll
            for (int p = 0; p < 4; p++) {
                __half hx = __float2half_rn(v[p * 2]);
                __half hy = __float2half_rn(v[p * 2 + 1]);
                __half lx = __float2half_rn(v[p * 2] - __half2float(hx));
                __half ly = __float2half_rn(v[p * 2 + 1] - __half2float(hy));
                __half2 h2 = __halves2half2(hx, hy), l2 = __halves2half2(lx, ly);
                hi[p] = *(uint32_t*)&h2;
                lo[p] = *(uint32_t*)&l2;
            }
            int cj = hh * 4 + c;
            uint32_t off = rowbase + (uint32_t)((cj ^ (r & 7)) << 4);
            *(uint4*)(smb + nAh + off) = make_uint4(hi[0], hi[1], hi[2], hi[3]);
            *(uint4*)(smb + nAl + off) = make_uint4(lo[0], lo[1], lo[2], lo[3]);
        }
    }
    __syncthreads();

    int m0 = (wid & 1) * 32;
    int n0 = (wid >> 1) * 64;
    float acc[2][8][4];
#pragma unroll
    for (int a = 0; a < 2; a++)
#pragma unroll
        for (int b = 0; b < 8; b++)
#pragma unroll
            for (int c = 0; c < 4; c++) acc[a][b][c] = 0.f;

    int arow0 = m0 + (lane & 15), arow1 = arow0 + 16;
    int bk_lane = lane & 15;
#pragma unroll
    for (int ks = 0; ks < 8; ks++) {
        int chunk = ks * 2 + (lane >> 4);
        uint32_t a0a = sb + nAh + (uint32_t)(arow0 * 256) + (uint32_t)((chunk ^ (arow0 & 7)) << 4);
        uint32_t a1a = sb + nAh + (uint32_t)(arow1 * 256) + (uint32_t)((chunk ^ (arow1 & 7)) << 4);
        uint32_t ah0[4], ah1[4], al0[4], al1[4];
        ldsm_x4(ah0, a0a);
        ldsm_x4(ah1, a1a);
        ldsm_x4(al0, a0a + 16384u);
        ldsm_x4(al1, a1a + 16384u);
        int bk = ks * 16 + bk_lane;
        uint32_t brow = sb + nB + (uint32_t)(bk * 512);
        int bsw = bk & 7;
#pragma unroll
        for (int nt = 0; nt < 8; nt++) {
            uint32_t bfr[2];
            ldsm_x2t(bfr, brow + (uint32_t)((((n0 >> 3) + nt) ^ bsw) << 4));
            mma16816(acc[0][nt], ah0, bfr);
            mma16816(acc[1][nt], ah1, bfr);
            mma16816(acc[0][nt], al0, bfr);
            mma16816(acc[1][nt], al1, bfr);
        }
    }

    {
        int cc = 2 * (lane & 3), rr = lane >> 2;
#pragma unroll
        for (int nt = 0; nt < 8; nt++) {
            int c_ = n0 + nt * 8 + cc;
            float2 bb = *(const float2*)&g_BPQ[c_];
#pragma unroll
            for (int mt = 0; mt < 2; mt++) {
                int r_ = row0 + m0 + mt * 16 + rr;
                if (r_ < NN)
                    *(float2*)&g_PQ[(size_t)r_ * 256 + c_] =
                        make_float2(acc[mt][nt][0] + bb.x, acc[mt][nt][1] + bb.y);
                if (r_ + 8 < NN)
                    *(float2*)&g_PQ[(size_t)(r_ + 8) * 256 + c_] =
                        make_float2(acc[mt][nt][2] + bb.x, acc[mt][nt][3] + bb.y);
            }
        }
    }
}

// ---------------- CSR build ----------------
__global__ void k_hist(const int* __restrict__ ei) {
    int e = blockIdx.x * blockDim.x + threadIdx.x;
    if (e < NE) atomicAdd(&g_cnt[ei[NE + e]], 1);
}
__global__ void k_scan() {
    __shared__ int s[1024];
    const int CH = 49;
    int t = threadIdx.x;
    int start = t * CH;
    int sum = 0;
    for (int i = 0; i < CH; i++) {
        int idx = start + i;
        if (idx < NN) sum += g_cnt[idx];
    }
    s[t] = sum;
    __syncthreads();
    for (int d = 1; d < 1024; d <<= 1) {
        int v = (t >= d) ? s[t - d] : 0;
        __syncthreads();
        s[t] += v;
        __syncthreads();
    }
    int run = s[t] - sum;
    for (int i = 0; i < CH; i++) {
        int idx = start + i;
        if (idx < NN) {
            g_cur[idx] = run;
            run += g_cnt[idx];
        }
    }
}
__global__ void k_scatter(const int* __restrict__ ei) {
    int e = blockIdx.x * blockDim.x + threadIdx.x;
    if (e < NE) {
        int d = ei[NE + e];
        int sr = ei[e];
        int pos = atomicAdd(&g_cur[d], 1);
        g_esrc[pos] = sr;
        g_edst[pos] = d;
    }
}

// ---------------- HMMA edge kernel (single-pass fp16, occ 2 — no spills) ----------------
#define oA  0u
#define oB  32768u
#define oB3 67584u
#define oSD 68096u
#define EDGE_SMEM 68608

__global__ void __launch_bounds__(256, 2) k_edge_mma(const float* __restrict__ b3,
                                                     float* __restrict__ out) {
    extern __shared__ char smb[];
    uint32_t sb = smem_u32(smb);
    int tid = threadIdx.x, lane = tid & 31, wid = tid >> 5;

    if (tid < 128) ((float*)(smb + oB3))[tid] = b3[tid];

#pragma unroll
    for (int q = tid; q < 2048; q += 256) {
        int k = q >> 4, cj = q & 15;
        uint4 pk = ((const uint4*)g_W3h)[q];
        *(uint4*)(smb + oB + (uint32_t)(k * 256) + (uint32_t)((cj ^ (k & 7)) << 4)) = pk;
    }

    {
        int r = tid & 127, hh = tid >> 7;
        int e = blockIdx.x * 128 + r;
        int dst = g_edst[e];
        int src = g_esrc[e];
        if (hh == 0) ((int*)(smb + oSD))[r] = dst;
        const float4* pv = (const float4*)(g_PQ + (size_t)dst * 256) + hh * 16;
        const float4* qv = (const float4*)(g_PQ + (size_t)src * 256 + 128) + hh * 16;
        uint32_t rowbase = (uint32_t)(r * 256);
#pragma unroll
        for (int c = 0; c < 8; c++) {
            float4 a0 = pv[c * 2], b0 = qv[c * 2];
            float4 a1 = pv[c * 2 + 1], b1 = qv[c * 2 + 1];
            __half2 h0 = __floats2half2_rn(fmaxf(a0.x + b0.x, 0.f), fmaxf(a0.y + b0.y, 0.f));
            __half2 h1 = __floats2half2_rn(fmaxf(a0.z + b0.z, 0.f), fmaxf(a0.w + b0.w, 0.f));
            __half2 h2 = __floats2half2_rn(fmaxf(a1.x + b1.x, 0.f), fmaxf(a1.y + b1.y, 0.f));
            __half2 h3 = __floats2half2_rn(fmaxf(a1.z + b1.z, 0.f), fmaxf(a1.w + b1.w, 0.f));
            int cj = hh * 8 + c;
            uint32_t off = rowbase + (uint32_t)((cj ^ (r & 7)) << 4);
            *(uint4*)(smb + oA + off) =
                make_uint4(*(uint32_t*)&h0, *(uint32_t*)&h1, *(uint32_t*)&h2, *(uint32_t*)&h3);
        }
    }
    __syncthreads();

    int m0 = (wid & 3) * 32;
    int n0 = (wid >> 2) * 64;
    float acc[2][8][4];
#pragma unroll
    for (int a = 0; a < 2; a++)
#pragma unroll
        for (int b = 0; b < 8; b++)
#pragma unroll
            for (int c = 0; c < 4; c++) acc[a][b][c] = 0.f;

    int arow0 = m0 + (lane & 15), arow1 = arow0 + 16;
    int bk_lane = lane & 15;
    uint32_t a0base = sb + oA + (uint32_t)(arow0 * 256);
    uint32_t a1base = sb + oA + (uint32_t)(arow1 * 256);
    int a0sw = arow0 & 7, a1sw = arow1 & 7;
#pragma unroll
    for (int ks = 0; ks < 8; ks++) {
        int chunk = ks * 2 + (lane >> 4);
        uint32_t ah0[4], ah1[4];
        ldsm_x4(ah0, a0base + (uint32_t)((chunk ^ a0sw) << 4));
        ldsm_x4(ah1, a1base + (uint32_t)((chunk ^ a1sw) << 4));
        int bk = ks * 16 + bk_lane;
        uint32_t brow = sb + oB + (uint32_t)(bk * 256);
        int bsw = bk & 7;
#pragma unroll
        for (int nt = 0; nt < 8; nt++) {
            uint32_t bfr[2];
            ldsm_x2t(bfr, brow + (uint32_t)((((n0 >> 3) + nt) ^ bsw) << 4));
            mma16816(acc[0][nt], ah0, bfr);
            mma16816(acc[1][nt], ah1, bfr);
        }
    }
    __syncthreads();

    float* accf = (float*)smb;
    {
        int rr = lane >> 2, cc = 2 * (lane & 3);
#pragma unroll
        for (int mt = 0; mt < 2; mt++)
#pragma unroll
            for (int nt = 0; nt < 8; nt++) {
                int r_ = m0 + mt * 16 + rr;
                int c_ = n0 + nt * 8 + cc;
                *(float2*)&accf[r_ * 132 + c_] = make_float2(acc[mt][nt][0], acc[mt][nt][1]);
                *(float2*)&accf[(r_ + 8) * 132 + c_] = make_float2(acc[mt][nt][2], acc[mt][nt][3]);
            }
    }
    __syncthreads();

    {
        int cg = tid & 31;
        int rg = tid >> 5;
        const float* b3s = (const float*)(smb + oB3);
        const int* sd = (const int*)(smb + oSD);
        float4 bias = *(const float4*)&b3s[cg * 4];
        int rbase = rg * 16;
        int curd = sd[rbase];
        float4 v = *(float4*)&accf[rbase * 132 + cg * 4];
        float4 mx = make_float4(fmaxf(v.x + bias.x, 0.f), fmaxf(v.y + bias.y, 0.f),
                                fmaxf(v.z + bias.z, 0.f), fmaxf(v.w + bias.w, 0.f));
#pragma unroll
        for (int i = 1; i < 16; i++) {
            int d = sd[rbase + i];
            float4 u = *(float4*)&accf[(rbase + i) * 132 + cg * 4];
            float4 w = make_float4(fmaxf(u.x + bias.x, 0.f), fmaxf(u.y + bias.y, 0.f),
                                   fmaxf(u.z + bias.z, 0.f), fmaxf(u.w + bias.w, 0.f));
            if (d != curd) {
                int* op = (int*)out + (size_t)curd * 128 + cg * 4;
                if (mx.x > 0.f) atomicMax(op + 0, __float_as_int(mx.x));
                if (mx.y > 0.f) atomicMax(op + 1, __float_as_int(mx.y));
                if (mx.z > 0.f) atomicMax(op + 2, __float_as_int(mx.z));
                if (mx.w > 0.f) atomicMax(op + 3, __float_as_int(mx.w));
                curd = d;
                mx = w;
            } else {
                mx.x = fmaxf(mx.x, w.x);
                mx.y = fmaxf(mx.y, w.y);
                mx.z = fmaxf(mx.z, w.z);
                mx.w = fmaxf(mx.w, w.w);
            }
        }
        int* op = (int*)out + (size_t)curd * 128 + cg * 4;
        if (mx.x > 0.f) atomicMax(op + 0, __float_as_int(mx.x));
        if (mx.y > 0.f) atomicMax(op + 1, __float_as_int(mx.y));
        if (mx.z > 0.f) atomicMax(op + 2, __float_as_int(mx.z));
        if (mx.w > 0.f) atomicMax(op + 3, __float_as_int(mx.w));
    }
}

// ---------------- launch ----------------
extern "C" void kernel_launch(void* const* d_in, const int* in_sizes, int n_in,
                              void* d_out, int out_size) {
    const float* x  = (const float*)d_in[0];
    const int*   ei = (const int*)d_in[1];
    const float* W1 = (const float*)d_in[2];
    const float* b1 = (const float*)d_in[3];
    const float* W2 = (const float*)d_in[4];
    const float* b2 = (const float*)d_in[5];
    const float* W3 = (const float*)d_in[6];
    const float* b3 = (const float*)d_in[7];
    float* out = (float*)d_out;

    cudaFuncSetAttribute(k_edge_mma, cudaFuncAttributeMaxDynamicSharedMemorySize, EDGE_SMEM);
    cudaFuncSetAttribute(k_node_hmma, cudaFuncAttributeMaxDynamicSharedMemorySize, NODE_SMEM);

    k_zero_out<<<(NN * 128 / 4 + 255) / 256, 256>>>((float4*)out, NN * 128 / 4);
    k_zero_cnt<<<(NN + 255) / 256, 256>>>();
    k_prep_w<<<128, 256>>>(W1, b1, W2, b2);
    k_prep_w3<<<64, 256>>>(W3);
    k_node_hmma<<<(NN + 63) / 64, 256, NODE_SMEM>>>(x);
    k_hist<<<NE / 256, 256>>>(ei);
    k_scan<<<1, 1024>>>();
    k_scatter<<<NE / 256, 256>>>(ei);
    k_edge_mma<<<NT, 256, EDGE_SMEM>>>(b3, out);
}

// round 7
// speedup vs baseline: 1.5962x; 1.2139x over previous
#include <cuda_runtime.h>
#include <cuda_fp16.h>
#include <cstdint>

#define NN 50000
#define NE 800000
#define NT (NE / 128)

// ---------------- device scratch ----------------
__device__ __align__(16) __half g_WPQh[128 * 256];     // fused node weights fp16 [k][col]
__device__ __align__(16) __half g_W3h[128 * 128];      // W3 fp16 [k][n]
__device__ __align__(16) float  g_BPQ[256];
__device__ __align__(16) __half g_PQh[(size_t)NN * 256]; // per-node [P|Q] fp16
__device__ int g_cnt[NN];
__device__ int g_cur[NN];
__device__ int g_esrc[NE];
__device__ int g_edst[NE];

// ---------------- helpers ----------------
__device__ __forceinline__ uint32_t smem_u32(const void* p) {
    uint32_t a;
    asm("{ .reg .u64 t; cvta.to.shared.u64 t, %1; cvt.u32.u64 %0, t; }" : "=r"(a) : "l"(p));
    return a;
}
__device__ __forceinline__ void ldsm_x4(uint32_t* r, uint32_t addr) {
    asm volatile("ldmatrix.sync.aligned.m8n8.x4.shared.b16 {%0,%1,%2,%3}, [%4];"
                 : "=r"(r[0]), "=r"(r[1]), "=r"(r[2]), "=r"(r[3]) : "r"(addr));
}
__device__ __forceinline__ void ldsm_x2t(uint32_t* r, uint32_t addr) {
    asm volatile("ldmatrix.sync.aligned.m8n8.x2.trans.shared.b16 {%0,%1}, [%2];"
                 : "=r"(r[0]), "=r"(r[1]) : "r"(addr));
}
__device__ __forceinline__ void mma16816(float* d, const uint32_t* a, const uint32_t* b) {
    asm volatile(
        "mma.sync.aligned.m16n8k16.row.col.f32.f16.f16.f32 "
        "{%0,%1,%2,%3}, {%4,%5,%6,%7}, {%8,%9}, {%0,%1,%2,%3};"
        : "+f"(d[0]), "+f"(d[1]), "+f"(d[2]), "+f"(d[3])
        : "r"(a[0]), "r"(a[1]), "r"(a[2]), "r"(a[3]), "r"(b[0]), "r"(b[1]));
}

// ---------------- init: zero out + zero cnt (one kernel) ----------------
__global__ void k_init(float4* out, int n4) {
    int i = blockIdx.x * blockDim.x + threadIdx.x;
    if (i < n4) out[i] = make_float4(0.f, 0.f, 0.f, 0.f);
    if (i < NN / 4) ((int4*)g_cnt)[i] = make_int4(0, 0, 0, 0);
}

// ---------------- weight prep: fused WPQ + W3 conversion ----------------
__global__ void k_prep_w(const float* __restrict__ W1, const float* __restrict__ b1,
                         const float* __restrict__ W2, const float* __restrict__ b2,
                         const float* __restrict__ W3) {
    int blk = blockIdx.x;
    if (blk >= 128) {                 // blocks 128..191: W3 -> fp16
        int q = (blk - 128) * 256 + threadIdx.x;
        g_W3h[q] = __float2half_rn(W3[q]);
        return;
    }
    __shared__ float w1row[128];
    int i = blk;
    if (threadIdx.x < 128) w1row[threadIdx.x] = W1[i * 128 + threadIdx.x];
    __syncthreads();
    int j = threadIdx.x;
    float acc = 0.f;
    if (j < 128) {
        for (int k = 0; k < 128; k++)
            acc += w1row[k] * (W2[k * 128 + j] - W2[(k + 128) * 128 + j]);
    } else {
        int jj = j - 128;
        for (int k = 0; k < 128; k++)
            acc += w1row[k] * W2[(k + 128) * 128 + jj];
    }
    g_WPQh[i * 256 + j] = __float2half_rn(acc);
    if (i == 0) {
        float b = 0.f;
        if (j < 128) {
            for (int k = 0; k < 128; k++)
                b += b1[k] * (W2[k * 128 + j] - W2[(k + 128) * 128 + j]);
            b += b2[j];
        } else {
            int jj = j - 128;
            for (int k = 0; k < 128; k++)
                b += b1[k] * W2[(k + 128) * 128 + jj];
        }
        g_BPQ[j] = b;
    }
}

// ---------------- node GEMM (HMMA, A=x split hi/lo exact, B=WPQ fp16) ----------------
#define nAh 0u
#define nAl 16384u
#define nB  32768u
#define NODE_SMEM 98304

__global__ void __launch_bounds__(256, 2) k_node_hmma(const float* __restrict__ x) {
    extern __shared__ char smb[];
    uint32_t sb = smem_u32(smb);
    int tid = threadIdx.x, lane = tid & 31, wid = tid >> 5;
    int row0 = blockIdx.x * 64;

#pragma unroll
    for (int q = tid; q < 4096; q += 256) {
        int k = q >> 5, cj = q & 31;
        uint4 pk = ((const uint4*)g_WPQh)[q];
        *(uint4*)(smb + nB + (uint32_t)(k * 512) + (uint32_t)((cj ^ (k & 7)) << 4)) = pk;
    }
    {
        int r = tid & 63, hh = tid >> 6;
        int row = row0 + r;
        const float4* xp = (const float4*)(x + (size_t)row * 128 + hh * 32);
        uint32_t rowbase = (uint32_t)(r * 256);
#pragma unroll
        for (int c = 0; c < 4; c++) {
            float4 f0, f1;
            if (row < NN) { f0 = xp[c * 2]; f1 = xp[c * 2 + 1]; }
            else { f0 = make_float4(0,0,0,0); f1 = f0; }
            float v[8] = {f0.x, f0.y, f0.z, f0.w, f1.x, f1.y, f1.z, f1.w};
            uint32_t hi[4], lo[4];
#pragma unroll
            for (int p = 0; p < 4; p++) {
                __half hx = __float2half_rn(v[p * 2]);
                __half hy = __float2half_rn(v[p * 2 + 1]);
                __half lx = __float2half_rn(v[p * 2] - __half2float(hx));
                __half ly = __float2half_rn(v[p * 2 + 1] - __half2float(hy));
                __half2 h2 = __halves2half2(hx, hy), l2 = __halves2half2(lx, ly);
                hi[p] = *(uint32_t*)&h2;
                lo[p] = *(uint32_t*)&l2;
            }
            int cj = hh * 4 + c;
            uint32_t off = rowbase + (uint32_t)((cj ^ (r & 7)) << 4);
            *(uint4*)(smb + nAh + off) = make_uint4(hi[0], hi[1], hi[2], hi[3]);
            *(uint4*)(smb + nAl + off) = make_uint4(lo[0], lo[1], lo[2], lo[3]);
        }
    }
    __syncthreads();

    int m0 = (wid & 1) * 32;
    int n0 = (wid >> 1) * 64;
    float acc[2][8][4];
#pragma unroll
    for (int a = 0; a < 2; a++)
#pragma unroll
        for (int b = 0; b < 8; b++)
#pragma unroll
            for (int c = 0; c < 4; c++) acc[a][b][c] = 0.f;

    int arow0 = m0 + (lane & 15), arow1 = arow0 + 16;
    int bk_lane = lane & 15;
#pragma unroll
    for (int ks = 0; ks < 8; ks++) {
        int chunk = ks * 2 + (lane >> 4);
        uint32_t a0a = sb + nAh + (uint32_t)(arow0 * 256) + (uint32_t)((chunk ^ (arow0 & 7)) << 4);
        uint32_t a1a = sb + nAh + (uint32_t)(arow1 * 256) + (uint32_t)((chunk ^ (arow1 & 7)) << 4);
        uint32_t ah0[4], ah1[4], al0[4], al1[4];
        ldsm_x4(ah0, a0a);
        ldsm_x4(ah1, a1a);
        ldsm_x4(al0, a0a + 16384u);
        ldsm_x4(al1, a1a + 16384u);
        int bk = ks * 16 + bk_lane;
        uint32_t brow = sb + nB + (uint32_t)(bk * 512);
        int bsw = bk & 7;
#pragma unroll
        for (int nt = 0; nt < 8; nt++) {
            uint32_t bfr[2];
            ldsm_x2t(bfr, brow + (uint32_t)((((n0 >> 3) + nt) ^ bsw) << 4));
            mma16816(acc[0][nt], ah0, bfr);
            mma16816(acc[1][nt], ah1, bfr);
            mma16816(acc[0][nt], al0, bfr);
            mma16816(acc[1][nt], al1, bfr);
        }
    }

    // epilogue: + bias, round to fp16, store packed half2 (one 32-bit STG per col-pair)
    {
        int cc = 2 * (lane & 3), rr = lane >> 2;
#pragma unroll
        for (int nt = 0; nt < 8; nt++) {
            int c_ = n0 + nt * 8 + cc;
            float2 bb = *(const float2*)&g_BPQ[c_];
#pragma unroll
            for (int mt = 0; mt < 2; mt++) {
                int r_ = row0 + m0 + mt * 16 + rr;
                if (r_ < NN) {
                    __half2 h = __floats2half2_rn(acc[mt][nt][0] + bb.x, acc[mt][nt][1] + bb.y);
                    *(uint32_t*)&g_PQh[(size_t)r_ * 256 + c_] = *(uint32_t*)&h;
                }
                if (r_ + 8 < NN) {
                    __half2 h = __floats2half2_rn(acc[mt][nt][2] + bb.x, acc[mt][nt][3] + bb.y);
                    *(uint32_t*)&g_PQh[(size_t)(r_ + 8) * 256 + c_] = *(uint32_t*)&h;
                }
            }
        }
    }
}

// ---------------- CSR build ----------------
__global__ void k_hist(const int* __restrict__ ei) {
    int e = blockIdx.x * blockDim.x + threadIdx.x;
    if (e < NE) atomicAdd(&g_cnt[ei[NE + e]], 1);
}
__global__ void k_scan() {
    __shared__ int s[1024];
    const int CH = 49;
    int t = threadIdx.x;
    int start = t * CH;
    int sum = 0;
    for (int i = 0; i < CH; i++) {
        int idx = start + i;
        if (idx < NN) sum += g_cnt[idx];
    }
    s[t] = sum;
    __syncthreads();
    for (int d = 1; d < 1024; d <<= 1) {
        int v = (t >= d) ? s[t - d] : 0;
        __syncthreads();
        s[t] += v;
        __syncthreads();
    }
    int run = s[t] - sum;
    for (int i = 0; i < CH; i++) {
        int idx = start + i;
        if (idx < NN) {
            g_cur[idx] = run;
            run += g_cnt[idx];
        }
    }
}
__global__ void k_scatter(const int* __restrict__ ei) {
    int e = blockIdx.x * blockDim.x + threadIdx.x;
    if (e < NE) {
        int d = ei[NE + e];
        int sr = ei[e];
        int pos = atomicAdd(&g_cur[d], 1);
        g_esrc[pos] = sr;
        g_edst[pos] = d;
    }
}

// ---------------- HMMA edge kernel (fp16 gather, single-pass, occ 2) ----------------
#define oA  0u
#define oB  32768u
#define oB3 67584u
#define oSD 68096u
#define EDGE_SMEM 68608

__global__ void __launch_bounds__(256, 2) k_edge_mma(const float* __restrict__ b3,
                                                     float* __restrict__ out) {
    extern __shared__ char smb[];
    uint32_t sb = smem_u32(smb);
    int tid = threadIdx.x, lane = tid & 31, wid = tid >> 5;

    if (tid < 128) ((float*)(smb + oB3))[tid] = b3[tid];

#pragma unroll
    for (int q = tid; q < 2048; q += 256) {
        int k = q >> 4, cj = q & 15;
        uint4 pk = ((const uint4*)g_W3h)[q];
        *(uint4*)(smb + oB + (uint32_t)(k * 256) + (uint32_t)((cj ^ (k & 7)) << 4)) = pk;
    }

    // build A = m1 = relu(P[dst] + Q[src]) — pure half2 math on fp16 PQ
    {
        int r = tid & 127, hh = tid >> 7;
        int e = blockIdx.x * 128 + r;
        int dst = g_edst[e];
        int src = g_esrc[e];
        if (hh == 0) ((int*)(smb + oSD))[r] = dst;
        const uint4* pv = (const uint4*)(g_PQh + (size_t)dst * 256);   // 32 chunks/row
        const uint4* qv = (const uint4*)(g_PQh + (size_t)src * 256);
        uint32_t rowbase = (uint32_t)(r * 256);
        const __half2 z = __float2half2_rn(0.f);
#pragma unroll
        for (int c = 0; c < 8; c++) {
            uint4 pk = pv[hh * 8 + c];            // P cols
            uint4 qk = qv[16 + hh * 8 + c];       // Q cols (offset 128 halves = 16 chunks)
            __half2 s0 = __hmax2(__hadd2(*(__half2*)&pk.x, *(__half2*)&qk.x), z);
            __half2 s1 = __hmax2(__hadd2(*(__half2*)&pk.y, *(__half2*)&qk.y), z);
            __half2 s2 = __hmax2(__hadd2(*(__half2*)&pk.z, *(__half2*)&qk.z), z);
            __half2 s3 = __hmax2(__hadd2(*(__half2*)&pk.w, *(__half2*)&qk.w), z);
            int cj = hh * 8 + c;
            uint32_t off = rowbase + (uint32_t)((cj ^ (r & 7)) << 4);
            *(uint4*)(smb + oA + off) =
                make_uint4(*(uint32_t*)&s0, *(uint32_t*)&s1, *(uint32_t*)&s2, *(uint32_t*)&s3);
        }
    }
    __syncthreads();

    int m0 = (wid & 3) * 32;
    int n0 = (wid >> 2) * 64;
    float acc[2][8][4];
#pragma unroll
    for (int a = 0; a < 2; a++)
#pragma unroll
        for (int b = 0; b < 8; b++)
#pragma unroll
            for (int c = 0; c < 4; c++) acc[a][b][c] = 0.f;

    int arow0 = m0 + (lane & 15), arow1 = arow0 + 16;
    int bk_lane = lane & 15;
    uint32_t a0base = sb + oA + (uint32_t)(arow0 * 256);
    uint32_t a1base = sb + oA + (uint32_t)(arow1 * 256);
    int a0sw = arow0 & 7, a1sw = arow1 & 7;
#pragma unroll
    for (int ks = 0; ks < 8; ks++) {
        int chunk = ks * 2 + (lane >> 4);
        uint32_t ah0[4], ah1[4];
        ldsm_x4(ah0, a0base + (uint32_t)((chunk ^ a0sw) << 4));
        ldsm_x4(ah1, a1base + (uint32_t)((chunk ^ a1sw) << 4));
        int bk = ks * 16 + bk_lane;
        uint32_t brow = sb + oB + (uint32_t)(bk * 256);
        int bsw = bk & 7;
#pragma unroll
        for (int nt = 0; nt < 8; nt++) {
            uint32_t bfr[2];
            ldsm_x2t(bfr, brow + (uint32_t)((((n0 >> 3) + nt) ^ bsw) << 4));
            mma16816(acc[0][nt], ah0, bfr);
            mma16816(acc[1][nt], ah1, bfr);
        }
    }
    __syncthreads();

    float* accf = (float*)smb;
    {
        int rr = lane >> 2, cc = 2 * (lane & 3);
#pragma unroll
        for (int mt = 0; mt < 2; mt++)
#pragma unroll
            for (int nt = 0; nt < 8; nt++) {
                int r_ = m0 + mt * 16 + rr;
                int c_ = n0 + nt * 8 + cc;
                *(float2*)&accf[r_ * 132 + c_] = make_float2(acc[mt][nt][0], acc[mt][nt][1]);
                *(float2*)&accf[(r_ + 8) * 132 + c_] = make_float2(acc[mt][nt][2], acc[mt][nt][3]);
            }
    }
    __syncthreads();

    {
        int cg = tid & 31;
        int rg = tid >> 5;
        const float* b3s = (const float*)(smb + oB3);
        const int* sd = (const int*)(smb + oSD);
        float4 bias = *(const float4*)&b3s[cg * 4];
        int rbase = rg * 16;
        int curd = sd[rbase];
        float4 v = *(float4*)&accf[rbase * 132 + cg * 4];
        float4 mx = make_float4(fmaxf(v.x + bias.x, 0.f), fmaxf(v.y + bias.y, 0.f),
                                fmaxf(v.z + bias.z, 0.f), fmaxf(v.w + bias.w, 0.f));
#pragma unroll
        for (int i = 1; i < 16; i++) {
            int d = sd[rbase + i];
            float4 u = *(float4*)&accf[(rbase + i) * 132 + cg * 4];
            float4 w = make_float4(fmaxf(u.x + bias.x, 0.f), fmaxf(u.y + bias.y, 0.f),
                                   fmaxf(u.z + bias.z, 0.f), fmaxf(u.w + bias.w, 0.f));
            if (d != curd) {
                int* op = (int*)out + (size_t)curd * 128 + cg * 4;
                if (mx.x > 0.f) atomicMax(op + 0, __float_as_int(mx.x));
                if (mx.y > 0.f) atomicMax(op + 1, __float_as_int(mx.y));
                if (mx.z > 0.f) atomicMax(op + 2, __float_as_int(mx.z));
                if (mx.w > 0.f) atomicMax(op + 3, __float_as_int(mx.w));
                curd = d;
                mx = w;
            } else {
                mx.x = fmaxf(mx.x, w.x);
                mx.y = fmaxf(mx.y, w.y);
                mx.z = fmaxf(mx.z, w.z);
                mx.w = fmaxf(mx.w, w.w);
            }
        }
        int* op = (int*)out + (size_t)curd * 128 + cg * 4;
        if (mx.x > 0.f) atomicMax(op + 0, __float_as_int(mx.x));
        if (mx.y > 0.f) atomicMax(op + 1, __float_as_int(mx.y));
        if (mx.z > 0.f) atomicMax(op + 2, __float_as_int(mx.z));
        if (mx.w > 0.f) atomicMax(op + 3, __float_as_int(mx.w));
    }
}

// ---------------- launch ----------------
extern "C" void kernel_launch(void* const* d_in, const int* in_sizes, int n_in,
                              void* d_out, int out_size) {
    const float* x  = (const float*)d_in[0];
    const int*   ei = (const int*)d_in[1];
    const float* W1 = (const float*)d_in[2];
    const float* b1 = (const float*)d_in[3];
    const float* W2 = (const float*)d_in[4];
    const float* b2 = (const float*)d_in[5];
    const float* W3 = (const float*)d_in[6];
    const float* b3 = (const float*)d_in[7];
    float* out = (float*)d_out;

    cudaFuncSetAttribute(k_edge_mma, cudaFuncAttributeMaxDynamicSharedMemorySize, EDGE_SMEM);
    cudaFuncSetAttribute(k_node_hmma, cudaFuncAttributeMaxDynamicSharedMemorySize, NODE_SMEM);

    k_init<<<(NN * 128 / 4 + 255) / 256, 256>>>((float4*)out, NN * 128 / 4);
    k_prep_w<<<192, 256>>>(W1, b1, W2, b2, W3);
    k_node_hmma<<<(NN + 63) / 64, 256, NODE_SMEM>>>(x);
    k_hist<<<NE / 256, 256>>>(ei);
    k_scan<<<1, 1024>>>();
    k_scatter<<<NE / 256, 256>>>(ei);
    k_edge_mma<<<NT, 256, EDGE_SMEM>>>(b3, out);
}